// round 11
// baseline (speedup 1.0000x reference)
#include <cuda_runtime.h>

#define NB 128      // batches
#define NP 27       // centers (3^3)
#define NN 8192     // points per batch
#define NS 512      // nsample
#define RAD2 0.0625f
#define BOXLIM 0.501f   // conservative candidate box: max|c_d| + r + margin

#define TPTS 1024                // points per compaction tile
#define NTILE (NN / TPTS)        // 8 tiles per batch

// ---- static scratch (no runtime allocation allowed) ----
__device__ float4 g_cand4[(size_t)NB * NN];   // per-tile locally-compacted candidates
__device__ int    g_tilecnt[NB * NTILE];      // candidate count per tile

// ============================================================
// Kernel 1: fused single-pass, per-tile order-preserving local
// compaction. grid = NB*NTILE = 1024, 256 thr, 4 points/thread.
// (unchanged from R9/R10 — measured ~3us)
// ============================================================
#define ST 256
#define SWARP (ST / 32)

__device__ __forceinline__ bool in_box(float x, float y, float z) {
    return (fabsf(x) <= BOXLIM) && (fabsf(y) <= BOXLIM) && (fabsf(z) <= BOXLIM);
}

__global__ __launch_bounds__(ST) void scatter_kernel(const float* __restrict__ xyz)
{
    const int tile = blockIdx.x;
    const int b = tile >> 3;              // / NTILE
    const int t = tile & (NTILE - 1);
    const float4* src4 = reinterpret_cast<const float4*>(
        xyz + (size_t)b * (NN * 3) + (size_t)t * (TPTS * 3));
    float4* dst = g_cand4 + (size_t)b * NN + (size_t)t * TPTS;

    __shared__ int s_w[SWARP];

    const int tid  = threadIdx.x;
    const int lane = tid & 31;
    const int warp = tid >> 5;

    const float4 va = src4[tid * 3 + 0];
    const float4 vb = src4[tid * 3 + 1];
    const float4 vc = src4[tid * 3 + 2];
    const bool m0 = in_box(va.x, va.y, va.z);
    const bool m1 = in_box(va.w, vb.x, vb.y);
    const bool m2 = in_box(vb.z, vb.w, vc.x);
    const bool m3 = in_box(vc.y, vc.z, vc.w);

    const int c = (int)m0 + (int)m1 + (int)m2 + (int)m3;

    int inc = c;
    #pragma unroll
    for (int d = 1; d < 32; d <<= 1) {
        const int v = __shfl_up_sync(0xffffffffu, inc, d);
        if (lane >= d) inc += v;
    }
    if (lane == 31) s_w[warp] = inc;
    __syncthreads();

    int base = 0, tot = 0;
    #pragma unroll
    for (int w = 0; w < SWARP; w++) {
        const int v = s_w[w];
        if (w < warp) base += v;
        tot += v;
    }

    int s = base + (inc - c);
    if (m0) dst[s++] = make_float4(va.x, va.y, va.z, 0.0f);
    if (m1) dst[s++] = make_float4(va.w, vb.x, vb.y, 0.0f);
    if (m2) dst[s++] = make_float4(vb.z, vb.w, vc.x, 0.0f);
    if (m3) dst[s++] = make_float4(vc.y, vc.z, vc.w, 0.0f);

    if (tid == 0) g_tilecnt[tile] = tot;
}

// ============================================================
// Kernel 2: ball query + group. 1 CTA per (batch, 9 centers).
// grid = NB*3 = 384, 512 threads. Candidate cached in registers
// (common case cnt <= 512); generic chunk loop kept for safety.
// ============================================================
#define NT 512
#define NWARP (NT / 32)         // 16
#define GSPLIT 3
#define GPC (NP / GSPLIT)       // 9 centers per CTA

__global__ __launch_bounds__(NT) void ballgroup_kernel(
    const float* __restrict__ xyz,
    const float* __restrict__ centers,
    float* __restrict__ out)
{
    const int bg = blockIdx.x;          // 0 .. NB*GSPLIT-1
    const int b  = bg / GSPLIT;
    const int g  = bg - b * GSPLIT;

    __shared__ int   s_pref[NTILE + 1];
    __shared__ int   s_wcnt[NWARP];
    __shared__ int   s_woff[NWARP + 1];
    __shared__ float s_cent[GPC * 3];
    __shared__ float s_first[3];

    const int tid  = threadIdx.x;
    const int lane = tid & 31;
    const int warp = tid >> 5;

    // ---- setup: tile-count prefix (warp 0) + stage centers ----
    if (warp == 0) {
        int c = (lane < NTILE) ? g_tilecnt[b * NTILE + lane] : 0;
        int inc = c;
        #pragma unroll
        for (int d = 1; d < NTILE; d <<= 1) {
            const int v = __shfl_up_sync(0xffffffffu, inc, d);
            if (lane >= d) inc += v;
        }
        if (lane < NTILE) s_pref[lane] = inc - c;      // exclusive
        if (lane == NTILE - 1) s_pref[NTILE] = inc;    // total
    }
    if (tid >= 32 && tid < 32 + GPC * 3)
        s_cent[tid - 32] = centers[g * GPC * 3 + (tid - 32)];
    __syncthreads();

    const int cnt = s_pref[NTILE];

    // ---- resolve tile indirection once; cache candidate in regs ----
    const float4* src = g_cand4 + (size_t)b * NN;
    const bool cvalid = tid < cnt;
    float rx, ry, rz;
    {
        const int ii = cvalid ? tid : 0;
        int tile = 0, lb = 0;
        #pragma unroll
        for (int w = 1; w < NTILE; w++) {
            const int pw = s_pref[w];
            if (ii >= pw) { tile = w; lb = pw; }
        }
        const float4 pt = src[tile * TPTS + (ii - lb)];
        rx = pt.x; ry = pt.y; rz = pt.z;
    }

    // batch point 0 for pad default (broadcast load)
    const float* pts0 = xyz + (size_t)b * (NN * 3);
    const float p0x = pts0[0], p0y = pts0[1], p0z = pts0[2];

    // ---- loop over this CTA's 9 centers ----
    for (int cc = 0; cc < GPC; cc++) {
        const float cx = s_cent[cc * 3 + 0];
        const float cy = s_cent[cc * 3 + 1];
        const float cz = s_cent[cc * 3 + 2];
        // c2 in the reference's association order (no fma)
        const float c2 = __fadd_rn(__fadd_rn(__fmul_rn(cx, cx), __fmul_rn(cy, cy)),
                                   __fmul_rn(cz, cz));
        float* o = out + (size_t)(b * NP + g * GPC + cc) * (NS * 3);

        __syncthreads();            // prev center's smem reads complete
        if (tid == 0) {
            // default pad: first_idx = 0 when no match
            s_first[0] = __fsub_rn(p0x, cx);
            s_first[1] = __fsub_rn(p0y, cy);
            s_first[2] = __fsub_rn(p0z, cz);
        }

        int basec = 0;
        for (int chunk = 0; chunk < cnt; chunk += NT) {
            bool valid; float x, y, z;
            if (chunk == 0) {
                valid = cvalid; x = rx; y = ry; z = rz;
            } else {                // rare generic path (cnt > NT)
                const int i = chunk + tid;
                valid = (i < cnt);
                const int ii = valid ? i : 0;
                int tile = 0, lb = 0;
                #pragma unroll
                for (int w = 1; w < NTILE; w++) {
                    const int pw = s_pref[w];
                    if (ii >= pw) { tile = w; lb = pw; }
                }
                const float4 pt = src[tile * TPTS + (ii - lb)];
                x = pt.x; y = pt.y; z = pt.z;
                __syncthreads();    // protect s_wcnt/s_first ordering on reload path
            }

            // dist2 = (x2 + c2) - 2*xc, exactly as the reference (mul/add, no fma)
            const float x2 = __fadd_rn(__fadd_rn(__fmul_rn(x, x), __fmul_rn(y, y)),
                                       __fmul_rn(z, z));
            const float xc = __fadd_rn(__fadd_rn(__fmul_rn(cx, x), __fmul_rn(cy, y)),
                                       __fmul_rn(cz, z));
            const float d2 = __fsub_rn(__fadd_rn(x2, c2), __fmul_rn(2.0f, xc));

            const bool m = valid && (d2 < RAD2);
            const unsigned bal = __ballot_sync(0xffffffffu, m);
            if (lane == 0) s_wcnt[warp] = __popc(bal);
            __syncthreads();

            // warp 0: exclusive scan of the 16 warp counts
            if (warp == 0) {
                int c = (lane < NWARP) ? s_wcnt[lane] : 0;
                int inc = c;
                #pragma unroll
                for (int d = 1; d < NWARP; d <<= 1) {
                    const int v = __shfl_up_sync(0xffffffffu, inc, d);
                    if (lane >= d) inc += v;
                }
                if (lane < NWARP) s_woff[lane] = inc - c;
                if (lane == NWARP - 1) s_woff[NWARP] = inc;
            }
            __syncthreads();

            if (m) {
                const int slot = basec + s_woff[warp] + __popc(bal & ((1u << lane) - 1u));
                if (slot < NS) {
                    const float ox = __fsub_rn(x, cx);
                    const float oy = __fsub_rn(y, cy);
                    const float oz = __fsub_rn(z, cz);
                    o[slot * 3 + 0] = ox;
                    o[slot * 3 + 1] = oy;
                    o[slot * 3 + 2] = oz;
                    if (slot == 0) {
                        s_first[0] = ox;
                        s_first[1] = oy;
                        s_first[2] = oz;
                    }
                }
            }

            basec += s_woff[NWARP];
            if (basec >= NS) break;
        }

        __syncthreads();            // s_first final
        const int count = basec < NS ? basec : NS;
        const float f0 = s_first[0];
        const float f1 = s_first[1];
        const float f2 = s_first[2];

        // ---- pad fill [count*3, NS*3) with repeating (f0,f1,f2) ----
        const int start = count * 3;                 // <= 1536
        const int head  = (4 - (start & 3)) & 3;

        if (tid < head && start + tid < NS * 3) {
            const int fi = start + tid;
            const int d = fi % 3;
            o[fi] = (d == 0) ? f0 : (d == 1) ? f1 : f2;
        }

        const float4 pat0 = make_float4(f0, f1, f2, f0);
        const float4 pat1 = make_float4(f1, f2, f0, f1);
        const float4 pat2 = make_float4(f2, f0, f1, f2);

        const int vstart = (start + head) >> 2;
        float4* o4 = reinterpret_cast<float4*>(o);
        for (int v = vstart + tid; v < (NS * 3) / 4; v += NT) {
            const int r = v % 3;
            o4[v] = (r == 0) ? pat0 : (r == 1) ? pat1 : pat2;
        }
    }
}

extern "C" void kernel_launch(void* const* d_in, const int* in_sizes, int n_in,
                              void* d_out, int out_size)
{
    const float* xyz     = (const float*)d_in[0];   // [128, 8192, 3]
    const float* centers = (const float*)d_in[1];   // [1, 27, 3]
    float* out = (float*)d_out;                      // [3456, 512, 3]

    scatter_kernel<<<NB * NTILE, ST>>>(xyz);
    ballgroup_kernel<<<NB * GSPLIT, NT>>>(xyz, centers, out);
}

// round 13
// speedup vs baseline: 1.0202x; 1.0202x over previous
#include <cuda_runtime.h>

#define NB 128      // batches
#define NP 27       // centers (3^3)
#define NN 8192     // points per batch
#define NS 512      // nsample
#define RAD2 0.0625f
#define BOXLIM 0.501f   // conservative candidate box: max|c_d| + r + margin

#define TPTS 1024                // points per compaction tile
#define NTILE (NN / TPTS)        // 8 tiles per batch

// ---- static scratch (no runtime allocation allowed) ----
__device__ float4 g_cand4[(size_t)NB * NN];   // per-tile locally-compacted candidates
__device__ int    g_tilecnt[NB * NTILE];      // candidate count per tile

// ============================================================
// Kernel 1: fused single-pass, per-tile order-preserving local
// compaction. grid = NB*NTILE = 1024, 256 thr, 4 points/thread.
// (unchanged — measured ~3us)
// ============================================================
#define ST 256
#define SWARP (ST / 32)

__device__ __forceinline__ bool in_box(float x, float y, float z) {
    return (fabsf(x) <= BOXLIM) && (fabsf(y) <= BOXLIM) && (fabsf(z) <= BOXLIM);
}

__global__ __launch_bounds__(ST) void scatter_kernel(const float* __restrict__ xyz)
{
    const int tile = blockIdx.x;
    const int b = tile >> 3;              // / NTILE
    const int t = tile & (NTILE - 1);
    const float4* src4 = reinterpret_cast<const float4*>(
        xyz + (size_t)b * (NN * 3) + (size_t)t * (TPTS * 3));
    float4* dst = g_cand4 + (size_t)b * NN + (size_t)t * TPTS;

    __shared__ int s_w[SWARP];

    const int tid  = threadIdx.x;
    const int lane = tid & 31;
    const int warp = tid >> 5;

    const float4 va = src4[tid * 3 + 0];
    const float4 vb = src4[tid * 3 + 1];
    const float4 vc = src4[tid * 3 + 2];
    const bool m0 = in_box(va.x, va.y, va.z);
    const bool m1 = in_box(va.w, vb.x, vb.y);
    const bool m2 = in_box(vb.z, vb.w, vc.x);
    const bool m3 = in_box(vc.y, vc.z, vc.w);

    const int c = (int)m0 + (int)m1 + (int)m2 + (int)m3;

    int inc = c;
    #pragma unroll
    for (int d = 1; d < 32; d <<= 1) {
        const int v = __shfl_up_sync(0xffffffffu, inc, d);
        if (lane >= d) inc += v;
    }
    if (lane == 31) s_w[warp] = inc;
    __syncthreads();

    int base = 0, tot = 0;
    #pragma unroll
    for (int w = 0; w < SWARP; w++) {
        const int v = s_w[w];
        if (w < warp) base += v;
        tot += v;
    }

    int s = base + (inc - c);
    if (m0) dst[s++] = make_float4(va.x, va.y, va.z, 0.0f);
    if (m1) dst[s++] = make_float4(va.w, vb.x, vb.y, 0.0f);
    if (m2) dst[s++] = make_float4(vb.z, vb.w, vc.x, 0.0f);
    if (m3) dst[s++] = make_float4(vc.y, vc.z, vc.w, 0.0f);

    if (tid == 0) g_tilecnt[tile] = tot;
}

// ============================================================
// Kernel 2: ball query + group. ONE WARP per (batch, center).
// No shared memory, no __syncthreads. grid = 3456/16 = 216 CTAs
// of 512 threads; global warp id = bp.
// ============================================================
#define NT 512
#define WPB (NT / 32)           // 16 warps per CTA
#define FULLM 0xffffffffu

__global__ __launch_bounds__(NT) void ballgroup_kernel(
    const float* __restrict__ xyz,
    const float* __restrict__ centers,
    float* __restrict__ out)
{
    const int lane = threadIdx.x & 31;
    const int bp   = blockIdx.x * WPB + (threadIdx.x >> 5);   // 0 .. NB*NP-1
    const int b    = bp / NP;
    const int p    = bp - b * NP;

    // ---- per-warp tile prefix (registers only) ----
    int tc = (lane < NTILE) ? g_tilecnt[b * NTILE + lane] : 0;
    int inc = tc;
    #pragma unroll
    for (int d = 1; d < NTILE; d <<= 1) {
        const int v = __shfl_up_sync(FULLM, inc, d);
        if (lane >= d) inc += v;
    }
    // every lane materializes the 8 exclusive prefixes + total
    int pref[NTILE];
    pref[0] = 0;
    #pragma unroll
    for (int w = 1; w < NTILE; w++)
        pref[w] = __shfl_sync(FULLM, inc, w - 1);
    const int cnt = __shfl_sync(FULLM, inc, NTILE - 1);

    // ---- center + c2 (reference association order, no fma) ----
    const float cx = centers[p * 3 + 0];
    const float cy = centers[p * 3 + 1];
    const float cz = centers[p * 3 + 2];
    const float c2 = __fadd_rn(__fadd_rn(__fmul_rn(cx, cx), __fmul_rn(cy, cy)),
                               __fmul_rn(cz, cz));

    // default pad: first_idx = 0 when no match (argmax of all-false)
    const float* pts0 = xyz + (size_t)b * (NN * 3);
    float f0 = __fsub_rn(pts0[0], cx);
    float f1 = __fsub_rn(pts0[1], cy);
    float f2 = __fsub_rn(pts0[2], cz);
    bool have_first = false;

    const float4* src = g_cand4 + (size_t)b * NN;
    float* o = out + (size_t)bp * (NS * 3);

    // ---- warp-serial order-preserving compaction over candidates ----
    int base = 0;
    for (int chunk = 0; chunk < cnt; chunk += 32) {
        const int i = chunk + lane;
        const bool valid = (i < cnt);
        const int ii = valid ? i : 0;

        // tile lookup against register prefix array
        int tile = 0, lb = 0;
        #pragma unroll
        for (int w = 1; w < NTILE; w++) {
            if (ii >= pref[w]) { tile = w; lb = pref[w]; }
        }
        const float4 pt = src[tile * TPTS + (ii - lb)];
        const float x = pt.x, y = pt.y, z = pt.z;

        // dist2 = (x2 + c2) - 2*xc, exactly as the reference (mul/add, no fma)
        const float x2 = __fadd_rn(__fadd_rn(__fmul_rn(x, x), __fmul_rn(y, y)),
                                   __fmul_rn(z, z));
        const float xc = __fadd_rn(__fadd_rn(__fmul_rn(cx, x), __fmul_rn(cy, y)),
                                   __fmul_rn(cz, z));
        const float d2 = __fsub_rn(__fadd_rn(x2, c2), __fmul_rn(2.0f, xc));

        const bool m = valid && (d2 < RAD2);
        const unsigned bal = __ballot_sync(FULLM, m);

        const float ox = __fsub_rn(x, cx);
        const float oy = __fsub_rn(y, cy);
        const float oz = __fsub_rn(z, cz);

        if (m) {
            const int slot = base + __popc(bal & ((1u << lane) - 1u));
            if (slot < NS) {
                o[slot * 3 + 0] = ox;
                o[slot * 3 + 1] = oy;
                o[slot * 3 + 2] = oz;
            }
        }

        if (!have_first && bal) {       // first matching point = pad value
            const int sl = __ffs(bal) - 1;
            f0 = __shfl_sync(FULLM, ox, sl);
            f1 = __shfl_sync(FULLM, oy, sl);
            f2 = __shfl_sync(FULLM, oz, sl);
            have_first = true;
        }

        base += __popc(bal);
        if (base >= NS) break;
    }

    // ---- pad fill of float range [count*3, NS*3) with repeating (f0,f1,f2) ----
    const int count = base < NS ? base : NS;
    const int start = count * 3;                 // <= 1536
    const int head  = (4 - (start & 3)) & 3;     // scalars to 16B alignment

    if (lane < head && start + lane < NS * 3) {
        const int fi = start + lane;
        const int d = fi % 3;
        o[fi] = (d == 0) ? f0 : (d == 1) ? f1 : f2;
    }

    const float4 pat0 = make_float4(f0, f1, f2, f0);
    const float4 pat1 = make_float4(f1, f2, f0, f1);
    const float4 pat2 = make_float4(f2, f0, f1, f2);

    const int vstart = (start + head) >> 2;
    float4* o4 = reinterpret_cast<float4*>(o);   // 6144B-aligned group base
    for (int v = vstart + lane; v < (NS * 3) / 4; v += 32) {
        const int r = v % 3;
        o4[v] = (r == 0) ? pat0 : (r == 1) ? pat1 : pat2;
    }
}

extern "C" void kernel_launch(void* const* d_in, const int* in_sizes, int n_in,
                              void* d_out, int out_size)
{
    const float* xyz     = (const float*)d_in[0];   // [128, 8192, 3]
    const float* centers = (const float*)d_in[1];   // [1, 27, 3]
    float* out = (float*)d_out;                      // [3456, 512, 3]

    scatter_kernel<<<NB * NTILE, ST>>>(xyz);
    ballgroup_kernel<<<(NB * NP) / WPB, NT>>>(xyz, centers, out);
}

// round 15
// speedup vs baseline: 1.2424x; 1.2178x over previous
#include <cuda_runtime.h>

#define NB 128      // batches
#define NP 27       // centers (3^3)
#define NN 8192     // points per batch
#define NS 512      // nsample
#define RAD2 0.0625f
#define BOXLIM 0.501f   // conservative candidate box: max|c_d| + r + margin

#define TPTS 1024                // points per compaction tile
#define NTILE (NN / TPTS)        // 8 tiles per batch

// ---- static scratch (no runtime allocation allowed) ----
__device__ float4 g_cand4[(size_t)NB * NN];   // per-tile locally-compacted candidates
__device__ int    g_tilecnt[NB * NTILE];      // candidate count per tile

// ============================================================
// Kernel 1: fused single-pass, per-tile order-preserving local
// compaction. grid = NB*NTILE = 1024, 256 thr, 4 points/thread.
// (unchanged — measured ~3us)
// ============================================================
#define ST 256
#define SWARP (ST / 32)

__device__ __forceinline__ bool in_box(float x, float y, float z) {
    return (fabsf(x) <= BOXLIM) && (fabsf(y) <= BOXLIM) && (fabsf(z) <= BOXLIM);
}

__global__ __launch_bounds__(ST) void scatter_kernel(const float* __restrict__ xyz)
{
    const int tile = blockIdx.x;
    const int b = tile >> 3;              // / NTILE
    const int t = tile & (NTILE - 1);
    const float4* src4 = reinterpret_cast<const float4*>(
        xyz + (size_t)b * (NN * 3) + (size_t)t * (TPTS * 3));
    float4* dst = g_cand4 + (size_t)b * NN + (size_t)t * TPTS;

    __shared__ int s_w[SWARP];

    const int tid  = threadIdx.x;
    const int lane = tid & 31;
    const int warp = tid >> 5;

    const float4 va = src4[tid * 3 + 0];
    const float4 vb = src4[tid * 3 + 1];
    const float4 vc = src4[tid * 3 + 2];
    const bool m0 = in_box(va.x, va.y, va.z);
    const bool m1 = in_box(va.w, vb.x, vb.y);
    const bool m2 = in_box(vb.z, vb.w, vc.x);
    const bool m3 = in_box(vc.y, vc.z, vc.w);

    const int c = (int)m0 + (int)m1 + (int)m2 + (int)m3;

    int inc = c;
    #pragma unroll
    for (int d = 1; d < 32; d <<= 1) {
        const int v = __shfl_up_sync(0xffffffffu, inc, d);
        if (lane >= d) inc += v;
    }
    if (lane == 31) s_w[warp] = inc;
    __syncthreads();

    int base = 0, tot = 0;
    #pragma unroll
    for (int w = 0; w < SWARP; w++) {
        const int v = s_w[w];
        if (w < warp) base += v;
        tot += v;
    }

    int s = base + (inc - c);
    if (m0) dst[s++] = make_float4(va.x, va.y, va.z, 0.0f);
    if (m1) dst[s++] = make_float4(va.w, vb.x, vb.y, 0.0f);
    if (m2) dst[s++] = make_float4(vb.z, vb.w, vc.x, 0.0f);
    if (m3) dst[s++] = make_float4(vc.y, vc.z, vc.w, 0.0f);

    if (tid == 0) g_tilecnt[tile] = tot;
}

// ============================================================
// Kernel 2: ball query + group. TWO warps per (batch, center).
// Warp A: candidates [0,256). Warp B: [256,cnt).
// Register-resident: issue all 8 chunk loads up front (MLP=8),
// then ballots/stores from registers. One 64-thread named
// barrier per pair exchanges warp A's match count.
// CTA = 256 thr = 4 pairs. grid = NB*NP/4 = 864.
// ============================================================
#define NT 256
#define NPAIR (NT / 64)         // 4 center-pairs per CTA
#define UNROLL 8                // 8 chunks x 32 = 256 candidates per warp
#define FULLM 0xffffffffu

#define PAIR_BAR(id) asm volatile("bar.sync %0, 64;" :: "r"(id) : "memory")

__global__ __launch_bounds__(NT) void ballgroup_kernel(
    const float* __restrict__ xyz,
    const float* __restrict__ centers,
    float* __restrict__ out)
{
    const int tid  = threadIdx.x;
    const int lane = tid & 31;
    const int wid  = tid >> 5;          // 0..7
    const int pair = wid >> 1;          // 0..3
    const int sub  = wid & 1;           // 0 = warp A, 1 = warp B
    const int bp   = blockIdx.x * NPAIR + pair;   // 0 .. NB*NP-1
    const int b    = bp / NP;
    const int p    = bp - b * NP;

    __shared__ int   s_cnt[NPAIR][2];
    __shared__ int   s_have[NPAIR][2];
    __shared__ float s_f[NPAIR][2][3];

    // ---- per-warp tile prefix (registers only) ----
    int tc = (lane < NTILE) ? g_tilecnt[b * NTILE + lane] : 0;
    int incp = tc;
    #pragma unroll
    for (int d = 1; d < NTILE; d <<= 1) {
        const int v = __shfl_up_sync(FULLM, incp, d);
        if (lane >= d) incp += v;
    }
    int pref[NTILE];
    pref[0] = 0;
    #pragma unroll
    for (int w = 1; w < NTILE; w++)
        pref[w] = __shfl_sync(FULLM, incp, w - 1);
    const int cnt = __shfl_sync(FULLM, incp, NTILE - 1);

    // ---- center + c2 (reference association order, no fma) ----
    const float cx = centers[p * 3 + 0];
    const float cy = centers[p * 3 + 1];
    const float cz = centers[p * 3 + 2];
    const float c2 = __fadd_rn(__fadd_rn(__fmul_rn(cx, cx), __fmul_rn(cy, cy)),
                               __fmul_rn(cz, cz));

    const float4* src = g_cand4 + (size_t)b * NN;
    float* o = out + (size_t)bp * (NS * 3);
    const int begin = sub * (UNROLL * 32);

    // ---- phase 1: batch-load my 8 chunks (MLP=8) ----
    float4 v[UNROLL];
    #pragma unroll
    for (int k = 0; k < UNROLL; k++) {
        const int i = begin + k * 32 + lane;
        const int ii = (i < cnt) ? i : 0;
        int tile = 0, lb = 0;
        #pragma unroll
        for (int w = 1; w < NTILE; w++)
            if (ii >= pref[w]) { tile = w; lb = pref[w]; }
        v[k] = src[tile * TPTS + (ii - lb)];
    }

    // ---- phase 2: ballots + recentered coords, all in registers ----
    unsigned bal[UNROLL];
    int cloc = 0;                 // matches in my range (register part)
    int have = 0;
    float ff0 = 0.f, ff1 = 0.f, ff2 = 0.f;   // first match in my range

    #pragma unroll
    for (int k = 0; k < UNROLL; k++) {
        const bool valid = (begin + k * 32 + lane) < cnt;
        const float x = v[k].x, y = v[k].y, z = v[k].z;

        // dist2 = (x2 + c2) - 2*xc, exactly as the reference (mul/add, no fma)
        const float x2 = __fadd_rn(__fadd_rn(__fmul_rn(x, x), __fmul_rn(y, y)),
                                   __fmul_rn(z, z));
        const float xc = __fadd_rn(__fadd_rn(__fmul_rn(cx, x), __fmul_rn(cy, y)),
                                   __fmul_rn(cz, z));
        const float d2 = __fsub_rn(__fadd_rn(x2, c2), __fmul_rn(2.0f, xc));

        const bool m = valid && (d2 < RAD2);
        bal[k] = __ballot_sync(FULLM, m);

        const float ox = __fsub_rn(x, cx);
        const float oy = __fsub_rn(y, cy);
        const float oz = __fsub_rn(z, cz);
        v[k].x = ox; v[k].y = oy; v[k].z = oz;

        if (!have && bal[k]) {           // uniform condition
            const int sl = __ffs(bal[k]) - 1;
            ff0 = __shfl_sync(FULLM, ox, sl);
            ff1 = __shfl_sync(FULLM, oy, sl);
            ff2 = __shfl_sync(FULLM, oz, sl);
            have = 1;
        }
        cloc += __popc(bal[k]);
    }

    // ---- publish my count/first; exchange within the pair ----
    if (lane == 0) {
        s_cnt[pair][sub]  = cloc;
        s_have[pair][sub] = have;
        s_f[pair][sub][0] = ff0;
        s_f[pair][sub][1] = ff1;
        s_f[pair][sub][2] = ff2;
    }
    PAIR_BAR(1 + pair);

    const int cA = s_cnt[pair][0];
    int base = sub ? cA : 0;

    // ---- phase 3: store matches from registers ----
    #pragma unroll
    for (int k = 0; k < UNROLL; k++) {
        const unsigned bk = bal[k];
        if ((bk >> lane) & 1u) {
            const int slot = base + __popc(bk & ((1u << lane) - 1u));
            if (slot < NS) {
                o[slot * 3 + 0] = v[k].x;
                o[slot * 3 + 1] = v[k].y;
                o[slot * 3 + 2] = v[k].z;
            }
        }
        base += __popc(bk);
    }

    // ---- rare tail: cnt > 512, warp B continues serially ----
    if (cnt > 2 * UNROLL * 32) {
        if (sub == 1) {
            for (int chunk = 2 * UNROLL * 32; chunk < cnt; chunk += 32) {
                const int i = chunk + lane;
                const bool valid = (i < cnt);
                const int ii = valid ? i : 0;
                int tile = 0, lb = 0;
                #pragma unroll
                for (int w = 1; w < NTILE; w++)
                    if (ii >= pref[w]) { tile = w; lb = pref[w]; }
                const float4 pt = src[tile * TPTS + (ii - lb)];
                const float x = pt.x, y = pt.y, z = pt.z;

                const float x2 = __fadd_rn(__fadd_rn(__fmul_rn(x, x), __fmul_rn(y, y)),
                                           __fmul_rn(z, z));
                const float xc = __fadd_rn(__fadd_rn(__fmul_rn(cx, x), __fmul_rn(cy, y)),
                                           __fmul_rn(cz, z));
                const float d2 = __fsub_rn(__fadd_rn(x2, c2), __fmul_rn(2.0f, xc));

                const bool m = valid && (d2 < RAD2);
                const unsigned bk = __ballot_sync(FULLM, m);

                const float ox = __fsub_rn(x, cx);
                const float oy = __fsub_rn(y, cy);
                const float oz = __fsub_rn(z, cz);

                if (m) {
                    const int slot = base + __popc(bk & ((1u << lane) - 1u));
                    if (slot < NS) {
                        o[slot * 3 + 0] = ox;
                        o[slot * 3 + 1] = oy;
                        o[slot * 3 + 2] = oz;
                    }
                }
                if (!have && bk) {
                    const int sl = __ffs(bk) - 1;
                    ff0 = __shfl_sync(FULLM, ox, sl);
                    ff1 = __shfl_sync(FULLM, oy, sl);
                    ff2 = __shfl_sync(FULLM, oz, sl);
                    have = 1;
                }
                base += __popc(bk);
                if (base >= NS) break;
            }
            if (lane == 0) {
                s_cnt[pair][1]  = base - cA;   // full B count incl. tail
                s_have[pair][1] = have;
                s_f[pair][1][0] = ff0;
                s_f[pair][1][1] = ff1;
                s_f[pair][1][2] = ff2;
            }
        }
        PAIR_BAR(1 + pair);     // republish before pad fill
    }

    // ---- pad fill: both warps, split range ----
    const int cB = s_cnt[pair][1];
    int total = cA + cB;
    const int count = total < NS ? total : NS;

    float f0, f1, f2;
    if (s_have[pair][0]) {
        f0 = s_f[pair][0][0]; f1 = s_f[pair][0][1]; f2 = s_f[pair][0][2];
    } else if (s_have[pair][1]) {
        f0 = s_f[pair][1][0]; f1 = s_f[pair][1][1]; f2 = s_f[pair][1][2];
    } else {
        // default pad: first_idx = 0 when no match (argmax of all-false)
        const float* pts0 = xyz + (size_t)b * (NN * 3);
        f0 = __fsub_rn(pts0[0], cx);
        f1 = __fsub_rn(pts0[1], cy);
        f2 = __fsub_rn(pts0[2], cz);
    }

    const int start = count * 3;                 // <= 1536
    const int head  = (4 - (start & 3)) & 3;     // scalars to 16B alignment

    if (sub == 0 && lane < head && start + lane < NS * 3) {
        const int fi = start + lane;
        const int d = fi % 3;
        o[fi] = (d == 0) ? f0 : (d == 1) ? f1 : f2;
    }

    const float4 pat0 = make_float4(f0, f1, f2, f0);
    const float4 pat1 = make_float4(f1, f2, f0, f1);
    const float4 pat2 = make_float4(f2, f0, f1, f2);

    const int vstart = (start + head) >> 2;
    const int vend   = (NS * 3) / 4;             // 384
    const int vmid   = (vstart + vend) >> 1;     // split between the two warps
    const int lo = sub ? vmid : vstart;
    const int hi = sub ? vend : vmid;

    float4* o4 = reinterpret_cast<float4*>(o);   // 6144B-aligned group base
    for (int vv = lo + lane; vv < hi; vv += 32) {
        const int r = vv % 3;
        o4[vv] = (r == 0) ? pat0 : (r == 1) ? pat1 : pat2;
    }
}

extern "C" void kernel_launch(void* const* d_in, const int* in_sizes, int n_in,
                              void* d_out, int out_size)
{
    const float* xyz     = (const float*)d_in[0];   // [128, 8192, 3]
    const float* centers = (const float*)d_in[1];   // [1, 27, 3]
    float* out = (float*)d_out;                      // [3456, 512, 3]

    scatter_kernel<<<NB * NTILE, ST>>>(xyz);
    ballgroup_kernel<<<(NB * NP) / NPAIR, NT>>>(xyz, centers, out);
}